// round 10
// baseline (speedup 1.0000x reference)
#include <cuda_runtime.h>
#include <cstdint>

// out(b, y, x) = bilinear sample of img_b at (y + 5 + py, x + 5 + px), zero
// outside [0, 522).
// FOUR output rows per thread, 4 consecutive px each, float4 everywhere.
// Output rows y..y+3 need source rows Y..Y+4: 5 source-row quad pairs
// (10 LDG.128) + 4 STG.128 serve 512 px per warp-row. Column offset/weight
// hoisted (validated R6: rel_err ~1.2e-5). Row alignment: 522 % 4 == 2, so
// source rows alternate shift M0 / (M0+2)&3 — one uniform 4-way template
// dispatch, zero per-pixel integer work. Worst-case aligned-quad read ends
// exactly at the buffer's last element (521*522 + 9 + 508 -> quad end
// 272483), so no overrun.

static constexpr int NPAD = 522;
static constexpr int NOUT = 512;
static constexpr int B    = 256;

__device__ __forceinline__ float comp(const float4& A, const float4& Bq, int i) {
    switch (i) {
    case 0: return A.x;  case 1: return A.y;  case 2: return A.z;  case 3: return A.w;
    case 4: return Bq.x; case 5: return Bq.y; case 6: return Bq.z; default: return Bq.w;
    }
}

template <int M0>
__device__ __forceinline__ void fast_quad(
    const float* __restrict__ base, float* __restrict__ o0,
    int tid, int Y, int X0, float wx, const float* __restrict__ wy)
{
    const int c0 = Y * NPAD + X0 + 4 * tid;

    // 5 source rows, 2 aligned quads each. All loads issued up front (MLP=10).
    float4 A[5], Bq[5];
    #pragma unroll
    for (int r = 0; r < 5; r++) {
        const int c = c0 + r * NPAD;
        const float4* q = reinterpret_cast<const float4*>(base + (c & ~3));
        A[r]  = __ldg(q);
        Bq[r] = __ldg(q + 1);
    }

    // Horizontal lerps: t[r][i] for taps [c+i, c+i+1], shift M0 for even
    // source rows, (M0+2)&3 for odd (522 % 4 == 2).
    float t[5][4];
    #pragma unroll
    for (int r = 0; r < 5; r++) {
        const int M = (r & 1) ? ((M0 + 2) & 3) : M0;
        #pragma unroll
        for (int i = 0; i < 4; i++) {
            const float a = comp(A[r], Bq[r], M + i);
            const float bb = comp(A[r], Bq[r], M + i + 1);
            t[r][i] = a + wx * (bb - a);
        }
    }

    // Vertical lerps + stores.
    #pragma unroll
    for (int r = 0; r < 4; r++) {
        float4 v;
        v.x = t[r][0] + wy[r] * (t[r + 1][0] - t[r][0]);
        v.y = t[r][1] + wy[r] * (t[r + 1][1] - t[r][1]);
        v.z = t[r][2] + wy[r] * (t[r + 1][2] - t[r][2]);
        v.w = t[r][3] + wy[r] * (t[r + 1][3] - t[r][3]);
        *reinterpret_cast<float4*>(o0 + (size_t)r * NOUT + 4 * tid) = v;
    }
}

__global__ __launch_bounds__(128) void extract_patches_kernel(
    const float* __restrict__ img,   // (B, 522, 522, 1)
    const float* __restrict__ pos,   // (B, 2)  [px, py]
    float* __restrict__ out)         // (B, 512, 512, 1)
{
    const int b   = blockIdx.z;
    const int y0  = blockIdx.y * 4;
    const int tid = threadIdx.x;

    const float px = __ldg(pos + 2 * b);
    const float py = __ldg(pos + 2 * b + 1);

    // Exact reference row arithmetic for all 4 output rows.
    float wy[4];
    int   Yr[4];
    #pragma unroll
    for (int r = 0; r < 4; r++) {
        const float sy = (float)(y0 + r + 5) + py;
        const float yf = floorf(sy);
        wy[r] = sy - yf;
        Yr[r] = (int)yf;
    }
    const int Y = Yr[0];

    const float s0  = 5.0f + px;
    const float x0f = floorf(s0);
    const float wx  = s0 - x0f;
    const int   X0  = (int)x0f;

    const float* base = img + (size_t)b * (NPAD * NPAD);
    float* o0 = out + ((size_t)b * NOUT + y0) * NOUT;

    const bool fast = (X0 >= 0) & (X0 <= 9) & (Y >= 0) & (Y <= NPAD - 5) &
                      (Yr[1] == Y + 1) & (Yr[2] == Y + 2) & (Yr[3] == Y + 3);

    if (fast) {
        const int m = (2 * Y + X0) & 3;   // uniform across block (4*tid % 4 == 0)
        switch (m) {
        case 0:  fast_quad<0>(base, o0, tid, Y, X0, wx, wy); break;
        case 1:  fast_quad<1>(base, o0, tid, Y, X0, wx, wy); break;
        case 2:  fast_quad<2>(base, o0, tid, Y, X0, wx, wy); break;
        default: fast_quad<3>(base, o0, tid, Y, X0, wx, wy); break;
        }
    } else {
        // Exact per-pixel path with full predication (handles zero fill).
        #pragma unroll
        for (int r = 0; r < 4; r++) {
            const int   yy   = y0 + r;
            const float sy   = (float)(yy + 5) + py;
            const float yf   = floorf(sy);
            const float wyp  = sy - yf;
            const int   Yi   = (int)yf;
            const bool vy0 = ((unsigned)Yi       < (unsigned)NPAD);
            const bool vy1 = ((unsigned)(Yi + 1) < (unsigned)NPAD);
            const float* rr = base + (ptrdiff_t)Yi * NPAD;
            float* orow = out + ((size_t)b * NOUT + yy) * NOUT;
            #pragma unroll
            for (int i = 0; i < 4; i++) {
                const int   x    = 4 * tid + i;
                const float sx   = (float)(x + 5) + px;
                const float xf   = floorf(sx);
                const float wxp  = sx - xf;
                const int   X    = (int)xf;
                const bool vx0 = ((unsigned)X       < (unsigned)NPAD);
                const bool vx1 = ((unsigned)(X + 1) < (unsigned)NPAD);
                const float* p0 = rr + X;
                float g00 = 0.0f, g01 = 0.0f, g10 = 0.0f, g11 = 0.0f;
                if (vy0 && vx0) g00 = __ldg(p0);
                if (vy0 && vx1) g01 = __ldg(p0 + 1);
                if (vy1 && vx0) g10 = __ldg(p0 + NPAD);
                if (vy1 && vx1) g11 = __ldg(p0 + NPAD + 1);
                const float top = g00 + wxp * (g01 - g00);
                const float bot = g10 + wxp * (g11 - g10);
                orow[x] = top + wyp * (bot - top);
            }
        }
    }
}

extern "C" void kernel_launch(void* const* d_in, const int* in_sizes, int n_in,
                              void* d_out, int out_size)
{
    const float* img = (const float*)d_in[0];   // padded_obj: 256*522*522*1 f32
    const float* pos = (const float*)d_in[1];   // positions:  256*2 f32
    float* out = (float*)d_out;                 // 256*512*512*1 f32

    dim3 block(128, 1, 1);
    dim3 grid(1, NOUT / 4, B);                  // (1, 128, 256)
    extract_patches_kernel<<<grid, block>>>(img, pos, out);
}